// round 14
// baseline (speedup 1.0000x reference)
#include <cuda_runtime.h>
#include <cuda_fp16.h>
#include <cstdint>
#include <math.h>

#define L_ 4096
#define D_ 1024
#define H_ 16
#define HD_ 64
#define M_ 4096

// ---------------- scratch (device globals; no cudaMalloc) -------------------
__device__ __align__(16) float  g_h[L_ * D_];              // fp32 residual
__device__ __align__(16) __half g_xln[L_ * D_];
__device__ __align__(16) __half g_qkv[L_ * 3 * D_];
__device__ __align__(16) __half g_attn[L_ * D_];
__device__ __align__(16) __half g_y[L_ * D_];
__device__ __align__(16) __half g_act[(size_t)L_ * M_];
__device__ __align__(16) __half g_wq[D_ * 3 * D_];
__device__ __align__(16) __half g_wo[D_ * D_];
__device__ __align__(16) __half g_w0[D_ * M_];
__device__ __align__(16) __half g_w1[M_ * D_];

// ---------------- helpers ---------------------------------------------------
__device__ __forceinline__ uint32_t packf16(float lo, float hi) {
    __half2 h = __floats2half2_rn(lo, hi);
    return *(uint32_t*)&h;
}
__device__ __forceinline__ void mma_f16(float* c, const uint32_t* a,
                                        uint32_t b0, uint32_t b1) {
    asm volatile(
        "mma.sync.aligned.m16n8k16.row.col.f32.f16.f16.f32 "
        "{%0,%1,%2,%3}, {%4,%5,%6,%7}, {%8,%9}, {%0,%1,%2,%3};"
        : "+f"(c[0]), "+f"(c[1]), "+f"(c[2]), "+f"(c[3])
        : "r"(a[0]), "r"(a[1]), "r"(a[2]), "r"(a[3]), "r"(b0), "r"(b1));
}
__device__ __forceinline__ uint32_t smem_u32(const void* p) {
    uint32_t a;
    asm("{ .reg .u64 t; cvta.to.shared.u64 t, %1; cvt.u32.u64 %0, t; }" : "=r"(a) : "l"(p));
    return a;
}
__device__ __forceinline__ void cp_async16(uint32_t dst, const void* src) {
    asm volatile("cp.async.cg.shared.global [%0], [%1], 16;" :: "r"(dst), "l"(src));
}
#define CP_COMMIT() asm volatile("cp.async.commit_group;" ::: "memory")
#define CP_WAIT1()  asm volatile("cp.async.wait_group 1;" ::: "memory")

__device__ __forceinline__ void ldm_x4(uint32_t* r, uint32_t addr) {
    asm volatile("ldmatrix.sync.aligned.m8n8.x4.shared.b16 {%0,%1,%2,%3}, [%4];"
                 : "=r"(r[0]), "=r"(r[1]), "=r"(r[2]), "=r"(r[3]) : "r"(addr));
}
__device__ __forceinline__ void ldm_x4t(uint32_t* r, uint32_t addr) {
    asm volatile("ldmatrix.sync.aligned.m8n8.x4.trans.shared.b16 {%0,%1,%2,%3}, [%4];"
                 : "=r"(r[0]), "=r"(r[1]), "=r"(r[2]), "=r"(r[3]) : "r"(addr));
}
__device__ __forceinline__ void ldm_x2(uint32_t& r0, uint32_t& r1, uint32_t addr) {
    asm volatile("ldmatrix.sync.aligned.m8n8.x2.shared.b16 {%0,%1}, [%2];"
                 : "=r"(r0), "=r"(r1) : "r"(addr));
}
__device__ __forceinline__ void ldm_x2t(uint32_t& r0, uint32_t& r1, uint32_t addr) {
    asm volatile("ldmatrix.sync.aligned.m8n8.x2.trans.shared.b16 {%0,%1}, [%2];"
                 : "=r"(r0), "=r"(r1) : "r"(addr));
}
__device__ __forceinline__ float gelu_exact(float x) {
    return 0.5f * x * (1.0f + erff(x * 0.70710678118654752f));
}

// ---------------- merged fp32 -> f16 weight conversion ----------------------
__global__ __launch_bounds__(256) void cvt_all_kernel(
    const float4* __restrict__ wqkv, const float4* __restrict__ wo,
    const float4* __restrict__ wfc0, const float4* __restrict__ wfc1,
    uint2* __restrict__ oq, uint2* __restrict__ oo,
    uint2* __restrict__ o0, uint2* __restrict__ o1)
{
    int i = blockIdx.x * 256 + threadIdx.x;
    const float4* src;
    uint2* dst;
    if (i < 786432)            { src = wqkv; dst = oq; }
    else if (i < 1048576)      { src = wo;   dst = oo; i -= 786432; }
    else if (i < 2097152)      { src = wfc0; dst = o0; i -= 1048576; }
    else if (i < 3145728)      { src = wfc1; dst = o1; i -= 2097152; }
    else return;
    const float4 v = src[i];
    uint2 o;
    o.x = packf16(v.x, v.y);
    o.y = packf16(v.z, v.w);
    dst[i] = o;
}

// ---------------- LayerNorm (fp32 in, f16 out) ------------------------------
__global__ __launch_bounds__(256) void ln_kernel(const float* __restrict__ x,
                                                 const float* __restrict__ gw,
                                                 const float* __restrict__ bw,
                                                 __half* __restrict__ y)
{
    __shared__ float sh[8];
    const int row  = blockIdx.x;
    const int tid  = threadIdx.x;
    const int lane = tid & 31, wp = tid >> 5;

    float4 v = *(const float4*)(x + (size_t)row * D_ + tid * 4);
    float s = v.x + v.y + v.z + v.w;
#pragma unroll
    for (int o = 16; o; o >>= 1) s += __shfl_xor_sync(0xffffffffu, s, o);
    if (lane == 0) sh[wp] = s;
    __syncthreads();
    float mean = 0.f;
#pragma unroll
    for (int i = 0; i < 8; i++) mean += sh[i];
    mean *= (1.0f / D_);
    __syncthreads();

    v.x -= mean; v.y -= mean; v.z -= mean; v.w -= mean;
    float q = v.x * v.x + v.y * v.y + v.z * v.z + v.w * v.w;
#pragma unroll
    for (int o = 16; o; o >>= 1) q += __shfl_xor_sync(0xffffffffu, q, o);
    if (lane == 0) sh[wp] = q;
    __syncthreads();
    float var = 0.f;
#pragma unroll
    for (int i = 0; i < 8; i++) var += sh[i];
    var *= (1.0f / D_);
    const float inv = rsqrtf(var + 1e-5f);

    const float4 g4 = *(const float4*)(gw + tid * 4);
    const float4 b4 = *(const float4*)(bw + tid * 4);
    uint2 o2;
    o2.x = packf16(v.x * inv * g4.x + b4.x, v.y * inv * g4.y + b4.y);
    o2.y = packf16(v.z * inv * g4.z + b4.z, v.w * inv * g4.w + b4.w);
    *(uint2*)(y + (size_t)row * D_ + tid * 4) = o2;
}

// ---------------- f16 GEMM 128x128, 4 warps of 64x64, 2 CTAs/SM -------------
// k64 chunks, 3-stage cp.async pipeline (half the syncs of k32/4-stage).
// A stage [128][144B] (16B-aligned rows, ldmatrix conflict-free: 9i mod 8),
// B stage [64][272B]. Fragments double-buffered across the 4 k16 steps.
#define GA_BYTES (128 * 144)
#define GB_BYTES (64 * 272)
#define GEMM_SMEM (3 * (GA_BYTES + GB_BYTES))   // 107520

// q,k pre-scale: sqrt(0.125 * log2(e)) so softmax runs in exp2 domain.
#define QK_SCALE 0.42466088958239446f

template <bool BIAS, bool GELU, bool RES, bool HOUT, bool ROPE>
__global__ __launch_bounds__(128, 2) void gemm_h(
    const __half* __restrict__ A, const __half* __restrict__ B,
    const float* __restrict__ bias, const float* __restrict__ res,
    const float* __restrict__ rf, void* __restrict__ Cv, int N, int K)
{
    extern __shared__ __align__(16) char gsm[];
    const uint32_t aBase = smem_u32(gsm);
    const uint32_t bBase = aBase + 3 * GA_BYTES;

    const int tid = threadIdx.x;
    const int lane = tid & 31, wid = tid >> 5;
    const int mwarp = wid >> 1, nwarp = wid & 1;
    const int g = lane >> 2, t = lane & 3;
    const int rowBase = blockIdx.y * 128;
    const int colBase = blockIdx.x * 128;

    float acc[4][8][4];
#pragma unroll
    for (int i = 0; i < 4; i++)
#pragma unroll
        for (int j = 0; j < 8; j++)
#pragma unroll
            for (int r = 0; r < 4; r++) acc[i][j][r] = 0.f;

    const int NC = K >> 6;   // k64 chunks

    auto issue = [&](int s, int c) {
        const int k0 = c << 6;
        const uint32_t as = aBase + s * GA_BYTES;
        const uint32_t bs = bBase + s * GB_BYTES;
        // A: 128 rows x 128 B  (1024 x 16B ops, 8 per thread)
#pragma unroll
        for (int i = 0; i < 8; i++) {
            const int idx = i * 128 + tid;
            const int row = idx >> 3, q = idx & 7;
            cp_async16(as + row * 144 + q * 16,
                       A + (size_t)(rowBase + row) * K + k0 + q * 8);
        }
        // B: 64 rows x 256 B  (1024 x 16B ops, 8 per thread)
#pragma unroll
        for (int i = 0; i < 8; i++) {
            const int idx = i * 128 + tid;
            const int row = idx >> 4, q = idx & 15;
            cp_async16(bs + row * 272 + q * 16,
                       B + (size_t)(k0 + row) * N + colBase + q * 8);
        }
    };

    issue(0, 0); CP_COMMIT();
    issue(1, 1); CP_COMMIT();

    uint32_t af[2][4][4], bf[2][8][2];

    auto ldfrag = [&](int fb, uint32_t aSt, uint32_t bSt, int kk) {
        const uint32_t aAddr = aSt + (mwarp * 64 + (lane & 15)) * 144
                                   + (kk + 8 * (lane >> 4)) * 2;
#pragma unroll
        for (int mt = 0; mt < 4; mt++)
            ldm_x4(af[fb][mt], aAddr + mt * 16 * 144);
        const uint32_t bAddr = bSt + (kk + (lane & 15)) * 272
                             + (nwarp * 64) * 2 + (lane >> 4) * 16;
#pragma unroll
        for (int nt2 = 0; nt2 < 4; nt2++) {
            uint32_t r[4];
            ldm_x4t(r, bAddr + nt2 * 32);
            bf[fb][2 * nt2][0] = r[0]; bf[fb][2 * nt2][1] = r[1];
            bf[fb][2 * nt2 + 1][0] = r[2]; bf[fb][2 * nt2 + 1][1] = r[3];
        }
    };

    for (int c = 0; c < NC; c++) {
        CP_WAIT1();
        __syncthreads();
        if (c + 2 < NC) issue((c + 2) % 3, c + 2);
        CP_COMMIT();

        const int st = c % 3;
        const uint32_t aSt = aBase + st * GA_BYTES;
        const uint32_t bSt = bBase + st * GB_BYTES;

        ldfrag(0, aSt, bSt, 0);
#pragma unroll
        for (int kk = 0; kk < 64; kk += 16) {
            const int fb = (kk >> 4) & 1;
            if (kk + 16 < 64) ldfrag(fb ^ 1, aSt, bSt, kk + 16);
#pragma unroll
            for (int mt = 0; mt < 4; mt++)
#pragma unroll
                for (int nt = 0; nt < 8; nt++)
                    mma_f16(acc[mt][nt], af[fb][mt], bf[fb][nt][0], bf[fb][nt][1]);
        }
    }

    // epilogue
#pragma unroll
    for (int mt = 0; mt < 4; mt++) {
        const int row0 = rowBase + mwarp * 64 + mt * 16 + g;
#pragma unroll
        for (int nt = 0; nt < 8; nt++) {
            const int col = colBase + nwarp * 64 + nt * 8 + 2 * t;
#pragma unroll
            for (int half = 0; half < 2; half++) {
                const int row = row0 + half * 8;
                float vx = acc[mt][nt][half * 2 + 0];
                float vy = acc[mt][nt][half * 2 + 1];
                if (BIAS) { vx += bias[col]; vy += bias[col + 1]; }
                if (GELU) { vx = gelu_exact(vx); vy = gelu_exact(vy); }
                if (ROPE) {
                    if (col < 2048) {   // q,k: scale into exp2 domain, rotate
                        const float2 cs = *(const float2*)(rf + (size_t)row * 64 + (col & 63));
                        const float a = vx * QK_SCALE;
                        const float b = vy * QK_SCALE;
                        vx = a * cs.x - b * cs.y;
                        vy = a * cs.y + b * cs.x;
                    }
                }
                if (RES) {
                    const float2 rr = *(const float2*)(res + (size_t)row * N + col);
                    vx += rr.x; vy += rr.y;
                }
                if (HOUT) {
                    *(__half2*)((__half*)Cv + (size_t)row * N + col) =
                        __floats2half2_rn(vx, vy);
                } else {
                    float2 o2; o2.x = vx; o2.y = vy;
                    *(float2*)((float*)Cv + (size_t)row * N + col) = o2;
                }
            }
        }
    }
}

// ---------------- f16 flash attention, 4 warps x 32 q-rows ------------------
// Grid 256 CTAs (single wave); each CTA processes 2 q-tiles sequentially.
// Softmax in exp2 domain (scale pre-folded into q,k).
#define AKV_BYTES (64 * 144)
#define ATTN_SMEM (128 * 144 + 3 * 2 * AKV_BYTES)   // 73728

__global__ __launch_bounds__(128, 2) void attn_tc_kernel(const __half* __restrict__ qkv,
                                                         __half* __restrict__ out)
{
    extern __shared__ __align__(16) char asm_[];
    const uint32_t qBase = smem_u32(asm_);
    const uint32_t kvBase = qBase + 128 * 144;

    const int tid = threadIdx.x, lane = tid & 31, wid = tid >> 5;
    const int g = lane >> 2, t = lane & 3;
    const int h = blockIdx.y, sg = blockIdx.z;
    const int m0 = wid * 32;

    for (int qi = 0; qi < 2; qi++) {
        const int q0 = sg * 1024 + (blockIdx.x + qi * 4) * 128;

        __syncthreads();   // protect SMEM reuse across q-tile iterations

#pragma unroll
        for (int i = 0; i < 8; i++) {
            const int idx = i * 128 + tid;
            const int row = idx >> 3, q = idx & 7;
            cp_async16(qBase + row * 144 + q * 16,
                       qkv + (size_t)(q0 + row) * 3072 + h * 64 + q * 8);
        }
        auto issueKV = [&](int s, int kt) {
            const int kb = sg * 1024 + kt * 64;
            const uint32_t kSt = kvBase + s * 2 * AKV_BYTES;
            const uint32_t vSt = kSt + AKV_BYTES;
#pragma unroll
            for (int i = 0; i < 4; i++) {
                const int idx = i * 128 + tid;
                const int row = idx >> 3, q = idx & 7;
                cp_async16(kSt + row * 144 + q * 16,
                           qkv + (size_t)(kb + row) * 3072 + 1024 + h * 64 + q * 8);
                cp_async16(vSt + row * 144 + q * 16,
                           qkv + (size_t)(kb + row) * 3072 + 2048 + h * 64 + q * 8);
            }
        };
        issueKV(0, 0); CP_COMMIT();
        issueKV(1, 1); CP_COMMIT();

        uint32_t qf[2][4][4];
        float mi[2][2], li[2][2];
        float ao[2][8][4];
#pragma unroll
        for (int mt = 0; mt < 2; mt++) {
            mi[mt][0] = mi[mt][1] = -3.0e38f;
            li[mt][0] = li[mt][1] = 0.f;
#pragma unroll
            for (int dt = 0; dt < 8; dt++)
#pragma unroll
                for (int r = 0; r < 4; r++) ao[mt][dt][r] = 0.f;
        }

        for (int kt = 0; kt < 16; kt++) {
            CP_WAIT1();
            __syncthreads();
            if (kt == 0) {
#pragma unroll
                for (int mt = 0; mt < 2; mt++) {
                    const uint32_t qAddr = qBase + (m0 + mt * 16 + (lane & 15)) * 144
                                         + (8 * (lane >> 4)) * 2;
#pragma unroll
                    for (int kc = 0; kc < 4; kc++)
                        ldm_x4(qf[mt][kc], qAddr + kc * 32);
                }
            }
            if (kt + 2 < 16) issueKV((kt + 2) % 3, kt + 2);
            CP_COMMIT();

            const uint32_t kSt = kvBase + (kt % 3) * 2 * AKV_BYTES;
            const uint32_t vSt = kSt + AKV_BYTES;

            float as[2][8][4];
#pragma unroll
            for (int mt = 0; mt < 2; mt++)
#pragma unroll
                for (int nt = 0; nt < 8; nt++)
#pragma unroll
                    for (int r = 0; r < 4; r++) as[mt][nt][r] = 0.f;
#pragma unroll
            for (int kc = 0; kc < 4; kc++) {
                const uint32_t kAddr = kSt + (lane & 7) * 144
                                     + (kc * 16 + 8 * ((lane >> 3) & 1)) * 2;
#pragma unroll
                for (int nt = 0; nt < 8; nt++) {
                    uint32_t b0, b1;
                    ldm_x2(b0, b1, kAddr + nt * 8 * 144);
                    mma_f16(as[0][nt], qf[0][kc], b0, b1);
                    mma_f16(as[1][nt], qf[1][kc], b0, b1);
                }
            }

#pragma unroll
            for (int mt = 0; mt < 2; mt++) {
#pragma unroll
                for (int hh = 0; hh < 2; hh++) {
                    float rm = -3.0e38f;
#pragma unroll
                    for (int nt = 0; nt < 8; nt++)
                        rm = fmaxf(rm, fmaxf(as[mt][nt][hh * 2], as[mt][nt][hh * 2 + 1]));
                    rm = fmaxf(rm, __shfl_xor_sync(0xffffffffu, rm, 1));
                    rm = fmaxf(rm, __shfl_xor_sync(0xffffffffu, rm, 2));
                    const float mn = fmaxf(mi[mt][hh], rm);
                    const float corr = exp2f(mi[mt][hh] - mn);
                    mi[mt][hh] = mn;
                    float rs = 0.f;
#pragma unroll
                    for (int nt = 0; nt < 8; nt++) {
                        const float p0 = exp2f(as[mt][nt][hh * 2] - mn);
                        const float p1 = exp2f(as[mt][nt][hh * 2 + 1] - mn);
                        as[mt][nt][hh * 2] = p0; as[mt][nt][hh * 2 + 1] = p1;
                        rs += p0 + p1;
                    }
                    rs += __shfl_xor_sync(0xffffffffu, rs, 1);
                    rs += __shfl_xor_sync(0xffffffffu, rs, 2);
                    li[mt][hh] = li[mt][hh] * corr + rs;
#pragma unroll
                    for (int dt = 0; dt < 8; dt++) {
                        ao[mt][dt][hh * 2] *= corr;
                        ao[mt][dt][hh * 2 + 1] *= corr;
                    }
                }
            }

#pragma unroll
            for (int kc = 0; kc < 4; kc++) {
                uint32_t pa[2][4];
#pragma unroll
                for (int mt = 0; mt < 2; mt++) {
                    pa[mt][0] = packf16(as[mt][2 * kc][0],     as[mt][2 * kc][1]);
                    pa[mt][1] = packf16(as[mt][2 * kc][2],     as[mt][2 * kc][3]);
                    pa[mt][2] = packf16(as[mt][2 * kc + 1][0], as[mt][2 * kc + 1][1]);
                    pa[mt][3] = packf16(as[mt][2 * kc + 1][2], as[mt][2 * kc + 1][3]);
                }
                const uint32_t vAddr = vSt + (kc * 16 + (lane & 15)) * 144;
#pragma unroll
                for (int dt = 0; dt < 8; dt++) {
                    uint32_t b0, b1;
                    ldm_x2t(b0, b1, vAddr + dt * 16);
                    mma_f16(ao[0][dt], pa[0], b0, b1);
                    mma_f16(ao[1][dt], pa[1], b0, b1);
                }
            }
        }

        // epilogue
#pragma unroll
        for (int mt = 0; mt < 2; mt++) {
            const float inv0 = 1.0f / li[mt][0];
            const float inv1 = 1.0f / li[mt][1];
            const int row0 = q0 + m0 + mt * 16 + g;
#pragma unroll
            for (int dt = 0; dt < 8; dt++) {
                const int col = h * 64 + dt * 8 + 2 * t;
                *(__half2*)(out + (size_t)row0 * 1024 + col) =
                    __floats2half2_rn(ao[mt][dt][0] * inv0, ao[mt][dt][1] * inv0);
                *(__half2*)(out + (size_t)(row0 + 8) * 1024 + col) =
                    __floats2half2_rn(ao[mt][dt][2] * inv1, ao[mt][dt][3] * inv1);
            }
        }
    }
}

// ---------------- launch ----------------------------------------------------
extern "C" void kernel_launch(void* const* d_in, const int* in_sizes, int n_in,
                              void* d_out, int out_size)
{
    const float* hs   = (const float*)d_in[0];
    const float* rope = (const float*)d_in[2];
    const float* ln0g = (const float*)d_in[3];
    const float* ln0b = (const float*)d_in[4];
    const float* ln1g = (const float*)d_in[5];
    const float* ln1b = (const float*)d_in[6];
    const float* wqkv = (const float*)d_in[7];
    const float* wo   = (const float*)d_in[8];
    const float* wfc0 = (const float*)d_in[9];
    const float* bfc0 = (const float*)d_in[10];
    const float* wfc1 = (const float*)d_in[11];
    const float* bfc1 = (const float*)d_in[12];
    float* out = (float*)d_out;

    float* h;
    __half *xln, *qkv, *attn, *y, *act, *wq, *wo_h, *w0, *w1;
    cudaGetSymbolAddress((void**)&h,    g_h);
    cudaGetSymbolAddress((void**)&xln,  g_xln);
    cudaGetSymbolAddress((void**)&qkv,  g_qkv);
    cudaGetSymbolAddress((void**)&attn, g_attn);
    cudaGetSymbolAddress((void**)&y,    g_y);
    cudaGetSymbolAddress((void**)&act,  g_act);
    cudaGetSymbolAddress((void**)&wq,   g_wq);
    cudaGetSymbolAddress((void**)&wo_h, g_wo);
    cudaGetSymbolAddress((void**)&w0,   g_w0);
    cudaGetSymbolAddress((void**)&w1,   g_w1);

    cudaFuncSetAttribute((const void*)gemm_h<false, false, false, true, true>,
                         cudaFuncAttributeMaxDynamicSharedMemorySize, GEMM_SMEM);
    cudaFuncSetAttribute((const void*)gemm_h<false, false, true, false, false>,
                         cudaFuncAttributeMaxDynamicSharedMemorySize, GEMM_SMEM);
    cudaFuncSetAttribute((const void*)gemm_h<true, true, false, true, false>,
                         cudaFuncAttributeMaxDynamicSharedMemorySize, GEMM_SMEM);
    cudaFuncSetAttribute((const void*)gemm_h<true, false, true, false, false>,
                         cudaFuncAttributeMaxDynamicSharedMemorySize, GEMM_SMEM);
    cudaFuncSetAttribute((const void*)attn_tc_kernel,
                         cudaFuncAttributeMaxDynamicSharedMemorySize, ATTN_SMEM);

    // 0. all weights -> f16 (single launch)
    cvt_all_kernel<<<(3145728 + 255) / 256, 256>>>(
        (const float4*)wqkv, (const float4*)wo, (const float4*)wfc0, (const float4*)wfc1,
        (uint2*)wq, (uint2*)wo_h, (uint2*)w0, (uint2*)w1);

    // 1. LN0 -> f16
    ln_kernel<<<L_, 256>>>(hs, ln0g, ln0b, xln);
    // 2. QKV (f16 out, RoPE + exp2-domain scale fused)
    gemm_h<false, false, false, true, true><<<dim3(24, 32), 128, GEMM_SMEM>>>(
        xln, wq, nullptr, nullptr, rope, qkv, 3 * D_, D_);
    // 3. attention -> f16 (256 CTAs, 2 q-tiles each: single wave)
    attn_tc_kernel<<<dim3(4, 16, 4), 128, ATTN_SMEM>>>(qkv, attn);
    // 4. h = hs + attn @ w_o   (fp32 out)
    gemm_h<false, false, true, false, false><<<dim3(8, 32), 128, GEMM_SMEM>>>(
        attn, wo_h, nullptr, hs, nullptr, h, D_, D_);
    // 5. LN1 -> f16
    ln_kernel<<<L_, 256>>>(h, ln1g, ln1b, y);
    // 6. act = gelu(y @ w_fc0 + b0)  (f16 out)
    gemm_h<true, true, false, true, false><<<dim3(32, 32), 128, GEMM_SMEM>>>(
        y, w0, bfc0, nullptr, nullptr, act, M_, D_);
    // 7. out = h + act @ w_fc1 + b1  (fp32 out)
    gemm_h<true, false, true, false, false><<<dim3(8, 32), 128, GEMM_SMEM>>>(
        act, w1, bfc1, h, nullptr, out, D_, M_);
}

// round 15
// speedup vs baseline: 1.1133x; 1.1133x over previous
#include <cuda_runtime.h>
#include <cuda_fp16.h>
#include <cstdint>
#include <math.h>

#define L_ 4096
#define D_ 1024
#define H_ 16
#define HD_ 64
#define M_ 4096

// ---------------- scratch (device globals; no cudaMalloc) -------------------
__device__ __align__(16) float  g_h[L_ * D_];              // fp32 residual
__device__ __align__(16) __half g_xln[L_ * D_];
__device__ __align__(16) __half g_qkv[L_ * 3 * D_];
__device__ __align__(16) __half g_attn[L_ * D_];
__device__ __align__(16) __half g_y[L_ * D_];
__device__ __align__(16) __half g_act[(size_t)L_ * M_];
__device__ __align__(16) __half g_wq[D_ * 3 * D_];
__device__ __align__(16) __half g_wo[D_ * D_];
__device__ __align__(16) __half g_w0[D_ * M_];
__device__ __align__(16) __half g_w1[M_ * D_];

// ---------------- helpers ---------------------------------------------------
__device__ __forceinline__ uint32_t packf16(float lo, float hi) {
    __half2 h = __floats2half2_rn(lo, hi);
    return *(uint32_t*)&h;
}
__device__ __forceinline__ void mma_f16(float* c, const uint32_t* a,
                                        uint32_t b0, uint32_t b1) {
    asm volatile(
        "mma.sync.aligned.m16n8k16.row.col.f32.f16.f16.f32 "
        "{%0,%1,%2,%3}, {%4,%5,%6,%7}, {%8,%9}, {%0,%1,%2,%3};"
        : "+f"(c[0]), "+f"(c[1]), "+f"(c[2]), "+f"(c[3])
        : "r"(a[0]), "r"(a[1]), "r"(a[2]), "r"(a[3]), "r"(b0), "r"(b1));
}
__device__ __forceinline__ uint32_t smem_u32(const void* p) {
    uint32_t a;
    asm("{ .reg .u64 t; cvta.to.shared.u64 t, %1; cvt.u32.u64 %0, t; }" : "=r"(a) : "l"(p));
    return a;
}
__device__ __forceinline__ void cp_async16(uint32_t dst, const void* src) {
    asm volatile("cp.async.cg.shared.global [%0], [%1], 16;" :: "r"(dst), "l"(src));
}
#define CP_COMMIT() asm volatile("cp.async.commit_group;" ::: "memory")
#define CP_WAIT3()  asm volatile("cp.async.wait_group 3;" ::: "memory")
#define CP_WAIT1()  asm volatile("cp.async.wait_group 1;" ::: "memory")

__device__ __forceinline__ void ldm_x4(uint32_t* r, uint32_t addr) {
    asm volatile("ldmatrix.sync.aligned.m8n8.x4.shared.b16 {%0,%1,%2,%3}, [%4];"
                 : "=r"(r[0]), "=r"(r[1]), "=r"(r[2]), "=r"(r[3]) : "r"(addr));
}
__device__ __forceinline__ void ldm_x4t(uint32_t* r, uint32_t addr) {
    asm volatile("ldmatrix.sync.aligned.m8n8.x4.trans.shared.b16 {%0,%1,%2,%3}, [%4];"
                 : "=r"(r[0]), "=r"(r[1]), "=r"(r[2]), "=r"(r[3]) : "r"(addr));
}
__device__ __forceinline__ void ldm_x2(uint32_t& r0, uint32_t& r1, uint32_t addr) {
    asm volatile("ldmatrix.sync.aligned.m8n8.x2.shared.b16 {%0,%1}, [%2];"
                 : "=r"(r0), "=r"(r1) : "r"(addr));
}
__device__ __forceinline__ void ldm_x2t(uint32_t& r0, uint32_t& r1, uint32_t addr) {
    asm volatile("ldmatrix.sync.aligned.m8n8.x2.trans.shared.b16 {%0,%1}, [%2];"
                 : "=r"(r0), "=r"(r1) : "r"(addr));
}
__device__ __forceinline__ float gelu_exact(float x) {
    return 0.5f * x * (1.0f + erff(x * 0.70710678118654752f));
}

// ---------------- merged fp32 -> f16 weight conversion ----------------------
__global__ __launch_bounds__(256) void cvt_all_kernel(
    const float4* __restrict__ wqkv, const float4* __restrict__ wo,
    const float4* __restrict__ wfc0, const float4* __restrict__ wfc1,
    uint2* __restrict__ oq, uint2* __restrict__ oo,
    uint2* __restrict__ o0, uint2* __restrict__ o1)
{
    int i = blockIdx.x * 256 + threadIdx.x;
    const float4* src;
    uint2* dst;
    if (i < 786432)            { src = wqkv; dst = oq; }
    else if (i < 1048576)      { src = wo;   dst = oo; i -= 786432; }
    else if (i < 2097152)      { src = wfc0; dst = o0; i -= 1048576; }
    else if (i < 3145728)      { src = wfc1; dst = o1; i -= 2097152; }
    else return;
    const float4 v = src[i];
    uint2 o;
    o.x = packf16(v.x, v.y);
    o.y = packf16(v.z, v.w);
    dst[i] = o;
}

// ---------------- LayerNorm (fp32 in, f16 out) ------------------------------
__global__ __launch_bounds__(256) void ln_kernel(const float* __restrict__ x,
                                                 const float* __restrict__ gw,
                                                 const float* __restrict__ bw,
                                                 __half* __restrict__ y)
{
    __shared__ float sh[8];
    const int row  = blockIdx.x;
    const int tid  = threadIdx.x;
    const int lane = tid & 31, wp = tid >> 5;

    float4 v = *(const float4*)(x + (size_t)row * D_ + tid * 4);
    float s = v.x + v.y + v.z + v.w;
#pragma unroll
    for (int o = 16; o; o >>= 1) s += __shfl_xor_sync(0xffffffffu, s, o);
    if (lane == 0) sh[wp] = s;
    __syncthreads();
    float mean = 0.f;
#pragma unroll
    for (int i = 0; i < 8; i++) mean += sh[i];
    mean *= (1.0f / D_);
    __syncthreads();

    v.x -= mean; v.y -= mean; v.z -= mean; v.w -= mean;
    float q = v.x * v.x + v.y * v.y + v.z * v.z + v.w * v.w;
#pragma unroll
    for (int o = 16; o; o >>= 1) q += __shfl_xor_sync(0xffffffffu, q, o);
    if (lane == 0) sh[wp] = q;
    __syncthreads();
    float var = 0.f;
#pragma unroll
    for (int i = 0; i < 8; i++) var += sh[i];
    var *= (1.0f / D_);
    const float inv = rsqrtf(var + 1e-5f);

    const float4 g4 = *(const float4*)(gw + tid * 4);
    const float4 b4 = *(const float4*)(bw + tid * 4);
    uint2 o2;
    o2.x = packf16(v.x * inv * g4.x + b4.x, v.y * inv * g4.y + b4.y);
    o2.y = packf16(v.z * inv * g4.z + b4.z, v.w * inv * g4.w + b4.w);
    *(uint2*)(y + (size_t)row * D_ + tid * 4) = o2;
}

// ---------------- f16 GEMM 128x128, 4 warps of 64x64, 2 CTAs/SM -------------
// k32 chunks, 5-stage cp.async pipeline (4 chunks in flight). Fragment sets
// double-buffered across the two k16 steps.
#define GA_BYTES (128 * 80)
#define GB_BYTES (32 * 272)
#define GEMM_SMEM (5 * (GA_BYTES + GB_BYTES))   // 94720

// q,k pre-scale: sqrt(0.125 * log2(e)) so softmax runs in exp2 domain.
#define QK_SCALE 0.42466088958239446f

template <bool BIAS, bool GELU, bool RES, bool HOUT, bool ROPE>
__global__ __launch_bounds__(128, 2) void gemm_h(
    const __half* __restrict__ A, const __half* __restrict__ B,
    const float* __restrict__ bias, const float* __restrict__ res,
    const float* __restrict__ rf, void* __restrict__ Cv, int N, int K)
{
    extern __shared__ __align__(16) char gsm[];
    const uint32_t aBase = smem_u32(gsm);
    const uint32_t bBase = aBase + 5 * GA_BYTES;

    const int tid = threadIdx.x;
    const int lane = tid & 31, wid = tid >> 5;
    const int mwarp = wid >> 1, nwarp = wid & 1;
    const int g = lane >> 2, t = lane & 3;
    const int rowBase = blockIdx.y * 128;
    const int colBase = blockIdx.x * 128;

    float acc[4][8][4];
#pragma unroll
    for (int i = 0; i < 4; i++)
#pragma unroll
        for (int j = 0; j < 8; j++)
#pragma unroll
            for (int r = 0; r < 4; r++) acc[i][j][r] = 0.f;

    const int NC = K >> 5;

    auto issue = [&](int s, int c) {
        const int k0 = c << 5;
        const uint32_t as = aBase + s * GA_BYTES;
        const uint32_t bs = bBase + s * GB_BYTES;
#pragma unroll
        for (int i = 0; i < 4; i++) {
            const int idx = i * 128 + tid;
            const int row = idx >> 2, q = idx & 3;
            cp_async16(as + row * 80 + q * 16,
                       A + (size_t)(rowBase + row) * K + k0 + q * 8);
        }
#pragma unroll
        for (int i = 0; i < 4; i++) {
            const int idx = i * 128 + tid;
            const int row = idx >> 4, q = idx & 15;
            cp_async16(bs + row * 272 + q * 16,
                       B + (size_t)(k0 + row) * N + colBase + q * 8);
        }
    };

    issue(0, 0); CP_COMMIT();
    issue(1, 1); CP_COMMIT();
    issue(2, 2); CP_COMMIT();
    issue(3, 3); CP_COMMIT();

    uint32_t af[2][4][4], bf[2][8][2];

    auto ldfrag = [&](int fb, uint32_t aSt, uint32_t bSt, int kk) {
        const uint32_t aAddr = aSt + (mwarp * 64 + (lane & 15)) * 80
                                   + (kk + 8 * (lane >> 4)) * 2;
#pragma unroll
        for (int mt = 0; mt < 4; mt++)
            ldm_x4(af[fb][mt], aAddr + mt * 16 * 80);
        const uint32_t bAddr = bSt + (kk + (lane & 15)) * 272
                             + (nwarp * 64) * 2 + (lane >> 4) * 16;
#pragma unroll
        for (int nt2 = 0; nt2 < 4; nt2++) {
            uint32_t r[4];
            ldm_x4t(r, bAddr + nt2 * 32);
            bf[fb][2 * nt2][0] = r[0]; bf[fb][2 * nt2][1] = r[1];
            bf[fb][2 * nt2 + 1][0] = r[2]; bf[fb][2 * nt2 + 1][1] = r[3];
        }
    };

    for (int c = 0; c < NC; c++) {
        CP_WAIT3();
        __syncthreads();
        if (c + 4 < NC) issue((c + 4) % 5, c + 4);
        CP_COMMIT();

        const int st = c % 5;
        const uint32_t aSt = aBase + st * GA_BYTES;
        const uint32_t bSt = bBase + st * GB_BYTES;

        ldfrag(0, aSt, bSt, 0);
#pragma unroll
        for (int kk = 0; kk < 32; kk += 16) {
            const int fb = (kk >> 4) & 1;
            if (kk + 16 < 32) ldfrag(fb ^ 1, aSt, bSt, kk + 16);
#pragma unroll
            for (int mt = 0; mt < 4; mt++)
#pragma unroll
                for (int nt = 0; nt < 8; nt++)
                    mma_f16(acc[mt][nt], af[fb][mt], bf[fb][nt][0], bf[fb][nt][1]);
        }
    }

    // epilogue
#pragma unroll
    for (int mt = 0; mt < 4; mt++) {
        const int row0 = rowBase + mwarp * 64 + mt * 16 + g;
#pragma unroll
        for (int nt = 0; nt < 8; nt++) {
            const int col = colBase + nwarp * 64 + nt * 8 + 2 * t;
#pragma unroll
            for (int half = 0; half < 2; half++) {
                const int row = row0 + half * 8;
                float vx = acc[mt][nt][half * 2 + 0];
                float vy = acc[mt][nt][half * 2 + 1];
                if (BIAS) { vx += bias[col]; vy += bias[col + 1]; }
                if (GELU) { vx = gelu_exact(vx); vy = gelu_exact(vy); }
                if (ROPE) {
                    if (col < 2048) {
                        const float2 cs = *(const float2*)(rf + (size_t)row * 64 + (col & 63));
                        const float a = vx * QK_SCALE;
                        const float b = vy * QK_SCALE;
                        vx = a * cs.x - b * cs.y;
                        vy = a * cs.y + b * cs.x;
                    }
                }
                if (RES) {
                    const float2 rr = *(const float2*)(res + (size_t)row * N + col);
                    vx += rr.x; vy += rr.y;
                }
                if (HOUT) {
                    *(__half2*)((__half*)Cv + (size_t)row * N + col) =
                        __floats2half2_rn(vx, vy);
                } else {
                    float2 o2; o2.x = vx; o2.y = vy;
                    *(float2*)((float*)Cv + (size_t)row * N + col) = o2;
                }
            }
        }
    }
}

// ---------------- f16 flash attention, 4 warps x 32 q-rows ------------------
// Grid 256 CTAs (single wave); each CTA processes 2 q-tiles sequentially.
// Softmax in exp2 domain (scale pre-folded into q,k).
#define AKV_BYTES (64 * 144)
#define ATTN_SMEM (128 * 144 + 3 * 2 * AKV_BYTES)   // 73728

__global__ __launch_bounds__(128, 2) void attn_tc_kernel(const __half* __restrict__ qkv,
                                                         __half* __restrict__ out)
{
    extern __shared__ __align__(16) char asm_[];
    const uint32_t qBase = smem_u32(asm_);
    const uint32_t kvBase = qBase + 128 * 144;

    const int tid = threadIdx.x, lane = tid & 31, wid = tid >> 5;
    const int g = lane >> 2, t = lane & 3;
    const int h = blockIdx.y, sg = blockIdx.z;
    const int m0 = wid * 32;

    for (int qi = 0; qi < 2; qi++) {
        const int q0 = sg * 1024 + (blockIdx.x + qi * 4) * 128;

        __syncthreads();   // protect SMEM reuse across q-tile iterations

#pragma unroll
        for (int i = 0; i < 8; i++) {
            const int idx = i * 128 + tid;
            const int row = idx >> 3, q = idx & 7;
            cp_async16(qBase + row * 144 + q * 16,
                       qkv + (size_t)(q0 + row) * 3072 + h * 64 + q * 8);
        }
        auto issueKV = [&](int s, int kt) {
            const int kb = sg * 1024 + kt * 64;
            const uint32_t kSt = kvBase + s * 2 * AKV_BYTES;
            const uint32_t vSt = kSt + AKV_BYTES;
#pragma unroll
            for (int i = 0; i < 4; i++) {
                const int idx = i * 128 + tid;
                const int row = idx >> 3, q = idx & 7;
                cp_async16(kSt + row * 144 + q * 16,
                           qkv + (size_t)(kb + row) * 3072 + 1024 + h * 64 + q * 8);
                cp_async16(vSt + row * 144 + q * 16,
                           qkv + (size_t)(kb + row) * 3072 + 2048 + h * 64 + q * 8);
            }
        };
        issueKV(0, 0); CP_COMMIT();
        issueKV(1, 1); CP_COMMIT();

        uint32_t qf[2][4][4];
        float mi[2][2], li[2][2];
        float ao[2][8][4];
#pragma unroll
        for (int mt = 0; mt < 2; mt++) {
            mi[mt][0] = mi[mt][1] = -3.0e38f;
            li[mt][0] = li[mt][1] = 0.f;
#pragma unroll
            for (int dt = 0; dt < 8; dt++)
#pragma unroll
                for (int r = 0; r < 4; r++) ao[mt][dt][r] = 0.f;
        }

        for (int kt = 0; kt < 16; kt++) {
            CP_WAIT1();
            __syncthreads();
            if (kt == 0) {
#pragma unroll
                for (int mt = 0; mt < 2; mt++) {
                    const uint32_t qAddr = qBase + (m0 + mt * 16 + (lane & 15)) * 144
                                         + (8 * (lane >> 4)) * 2;
#pragma unroll
                    for (int kc = 0; kc < 4; kc++)
                        ldm_x4(qf[mt][kc], qAddr + kc * 32);
                }
            }
            if (kt + 2 < 16) issueKV((kt + 2) % 3, kt + 2);
            CP_COMMIT();

            const uint32_t kSt = kvBase + (kt % 3) * 2 * AKV_BYTES;
            const uint32_t vSt = kSt + AKV_BYTES;

            float as[2][8][4];
#pragma unroll
            for (int mt = 0; mt < 2; mt++)
#pragma unroll
                for (int nt = 0; nt < 8; nt++)
#pragma unroll
                    for (int r = 0; r < 4; r++) as[mt][nt][r] = 0.f;
#pragma unroll
            for (int kc = 0; kc < 4; kc++) {
                const uint32_t kAddr = kSt + (lane & 7) * 144
                                     + (kc * 16 + 8 * ((lane >> 3) & 1)) * 2;
#pragma unroll
                for (int nt = 0; nt < 8; nt++) {
                    uint32_t b0, b1;
                    ldm_x2(b0, b1, kAddr + nt * 8 * 144);
                    mma_f16(as[0][nt], qf[0][kc], b0, b1);
                    mma_f16(as[1][nt], qf[1][kc], b0, b1);
                }
            }

#pragma unroll
            for (int mt = 0; mt < 2; mt++) {
#pragma unroll
                for (int hh = 0; hh < 2; hh++) {
                    float rm = -3.0e38f;
#pragma unroll
                    for (int nt = 0; nt < 8; nt++)
                        rm = fmaxf(rm, fmaxf(as[mt][nt][hh * 2], as[mt][nt][hh * 2 + 1]));
                    rm = fmaxf(rm, __shfl_xor_sync(0xffffffffu, rm, 1));
                    rm = fmaxf(rm, __shfl_xor_sync(0xffffffffu, rm, 2));
                    const float mn = fmaxf(mi[mt][hh], rm);
                    const float corr = exp2f(mi[mt][hh] - mn);
                    mi[mt][hh] = mn;
                    float rs = 0.f;
#pragma unroll
                    for (int nt = 0; nt < 8; nt++) {
                        const float p0 = exp2f(as[mt][nt][hh * 2] - mn);
                        const float p1 = exp2f(as[mt][nt][hh * 2 + 1] - mn);
                        as[mt][nt][hh * 2] = p0; as[mt][nt][hh * 2 + 1] = p1;
                        rs += p0 + p1;
                    }
                    rs += __shfl_xor_sync(0xffffffffu, rs, 1);
                    rs += __shfl_xor_sync(0xffffffffu, rs, 2);
                    li[mt][hh] = li[mt][hh] * corr + rs;
#pragma unroll
                    for (int dt = 0; dt < 8; dt++) {
                        ao[mt][dt][hh * 2] *= corr;
                        ao[mt][dt][hh * 2 + 1] *= corr;
                    }
                }
            }

#pragma unroll
            for (int kc = 0; kc < 4; kc++) {
                uint32_t pa[2][4];
#pragma unroll
                for (int mt = 0; mt < 2; mt++) {
                    pa[mt][0] = packf16(as[mt][2 * kc][0],     as[mt][2 * kc][1]);
                    pa[mt][1] = packf16(as[mt][2 * kc][2],     as[mt][2 * kc][3]);
                    pa[mt][2] = packf16(as[mt][2 * kc + 1][0], as[mt][2 * kc + 1][1]);
                    pa[mt][3] = packf16(as[mt][2 * kc + 1][2], as[mt][2 * kc + 1][3]);
                }
                const uint32_t vAddr = vSt + (kc * 16 + (lane & 15)) * 144;
#pragma unroll
                for (int dt = 0; dt < 8; dt++) {
                    uint32_t b0, b1;
                    ldm_x2t(b0, b1, vAddr + dt * 16);
                    mma_f16(ao[0][dt], pa[0], b0, b1);
                    mma_f16(ao[1][dt], pa[1], b0, b1);
                }
            }
        }

        // epilogue
#pragma unroll
        for (int mt = 0; mt < 2; mt++) {
            const float inv0 = 1.0f / li[mt][0];
            const float inv1 = 1.0f / li[mt][1];
            const int row0 = q0 + m0 + mt * 16 + g;
#pragma unroll
            for (int dt = 0; dt < 8; dt++) {
                const int col = h * 64 + dt * 8 + 2 * t;
                *(__half2*)(out + (size_t)row0 * 1024 + col) =
                    __floats2half2_rn(ao[mt][dt][0] * inv0, ao[mt][dt][1] * inv0);
                *(__half2*)(out + (size_t)(row0 + 8) * 1024 + col) =
                    __floats2half2_rn(ao[mt][dt][2] * inv1, ao[mt][dt][3] * inv1);
            }
        }
    }
}

// ---------------- launch ----------------------------------------------------
extern "C" void kernel_launch(void* const* d_in, const int* in_sizes, int n_in,
                              void* d_out, int out_size)
{
    const float* hs   = (const float*)d_in[0];
    const float* rope = (const float*)d_in[2];
    const float* ln0g = (const float*)d_in[3];
    const float* ln0b = (const float*)d_in[4];
    const float* ln1g = (const float*)d_in[5];
    const float* ln1b = (const float*)d_in[6];
    const float* wqkv = (const float*)d_in[7];
    const float* wo   = (const float*)d_in[8];
    const float* wfc0 = (const float*)d_in[9];
    const float* bfc0 = (const float*)d_in[10];
    const float* wfc1 = (const float*)d_in[11];
    const float* bfc1 = (const float*)d_in[12];
    float* out = (float*)d_out;

    float* h;
    __half *xln, *qkv, *attn, *y, *act, *wq, *wo_h, *w0, *w1;
    cudaGetSymbolAddress((void**)&h,    g_h);
    cudaGetSymbolAddress((void**)&xln,  g_xln);
    cudaGetSymbolAddress((void**)&qkv,  g_qkv);
    cudaGetSymbolAddress((void**)&attn, g_attn);
    cudaGetSymbolAddress((void**)&y,    g_y);
    cudaGetSymbolAddress((void**)&act,  g_act);
    cudaGetSymbolAddress((void**)&wq,   g_wq);
    cudaGetSymbolAddress((void**)&wo_h, g_wo);
    cudaGetSymbolAddress((void**)&w0,   g_w0);
    cudaGetSymbolAddress((void**)&w1,   g_w1);

    cudaFuncSetAttribute((const void*)gemm_h<false, false, false, true, true>,
                         cudaFuncAttributeMaxDynamicSharedMemorySize, GEMM_SMEM);
    cudaFuncSetAttribute((const void*)gemm_h<false, false, true, false, false>,
                         cudaFuncAttributeMaxDynamicSharedMemorySize, GEMM_SMEM);
    cudaFuncSetAttribute((const void*)gemm_h<true, true, false, true, false>,
                         cudaFuncAttributeMaxDynamicSharedMemorySize, GEMM_SMEM);
    cudaFuncSetAttribute((const void*)gemm_h<true, false, true, false, false>,
                         cudaFuncAttributeMaxDynamicSharedMemorySize, GEMM_SMEM);
    cudaFuncSetAttribute((const void*)attn_tc_kernel,
                         cudaFuncAttributeMaxDynamicSharedMemorySize, ATTN_SMEM);

    // 0. all weights -> f16 (single launch)
    cvt_all_kernel<<<(3145728 + 255) / 256, 256>>>(
        (const float4*)wqkv, (const float4*)wo, (const float4*)wfc0, (const float4*)wfc1,
        (uint2*)wq, (uint2*)wo_h, (uint2*)w0, (uint2*)w1);

    // 1. LN0 -> f16
    ln_kernel<<<L_, 256>>>(hs, ln0g, ln0b, xln);
    // 2. QKV (f16 out, RoPE + exp2-domain scale fused)
    gemm_h<false, false, false, true, true><<<dim3(24, 32), 128, GEMM_SMEM>>>(
        xln, wq, nullptr, nullptr, rope, qkv, 3 * D_, D_);
    // 3. attention -> f16 (256 CTAs, 2 q-tiles each: single wave)
    attn_tc_kernel<<<dim3(4, 16, 4), 128, ATTN_SMEM>>>(qkv, attn);
    // 4. h = hs + attn @ w_o   (fp32 out)
    gemm_h<false, false, true, false, false><<<dim3(8, 32), 128, GEMM_SMEM>>>(
        attn, wo_h, nullptr, hs, nullptr, h, D_, D_);
    // 5. LN1 -> f16
    ln_kernel<<<L_, 256>>>(h, ln1g, ln1b, y);
    // 6. act = gelu(y @ w_fc0 + b0)  (f16 out)
    gemm_h<true, true, false, true, false><<<dim3(32, 32), 128, GEMM_SMEM>>>(
        y, w0, bfc0, nullptr, nullptr, act, M_, D_);
    // 7. out = h + act @ w_fc1 + b1  (fp32 out)
    gemm_h<true, false, true, false, false><<<dim3(8, 32), 128, GEMM_SMEM>>>(
        act, w1, bfc1, h, nullptr, out, D_, M_);
}

// round 16
// speedup vs baseline: 1.1413x; 1.0252x over previous
#include <cuda_runtime.h>
#include <cuda_fp16.h>
#include <cstdint>
#include <math.h>

#define L_ 4096
#define D_ 1024
#define H_ 16
#define HD_ 64
#define M_ 4096

// ---------------- scratch (device globals; no cudaMalloc) -------------------
__device__ __align__(16) float  g_h[L_ * D_];              // fp32 residual
__device__ __align__(16) __half g_xln[L_ * D_];
__device__ __align__(16) __half g_qkv[L_ * 3 * D_];
__device__ __align__(16) __half g_attn[L_ * D_];
__device__ __align__(16) __half g_y[L_ * D_];
__device__ __align__(16) __half g_act[(size_t)L_ * M_];
__device__ __align__(16) __half g_wq[D_ * 3 * D_];
__device__ __align__(16) __half g_wo[D_ * D_];
__device__ __align__(16) __half g_w0[D_ * M_];
__device__ __align__(16) __half g_w1[M_ * D_];

// ---------------- helpers ---------------------------------------------------
__device__ __forceinline__ uint32_t packf16(float lo, float hi) {
    __half2 h = __floats2half2_rn(lo, hi);
    return *(uint32_t*)&h;
}
__device__ __forceinline__ void mma_f16(float* c, const uint32_t* a,
                                        uint32_t b0, uint32_t b1) {
    asm volatile(
        "mma.sync.aligned.m16n8k16.row.col.f32.f16.f16.f32 "
        "{%0,%1,%2,%3}, {%4,%5,%6,%7}, {%8,%9}, {%0,%1,%2,%3};"
        : "+f"(c[0]), "+f"(c[1]), "+f"(c[2]), "+f"(c[3])
        : "r"(a[0]), "r"(a[1]), "r"(a[2]), "r"(a[3]), "r"(b0), "r"(b1));
}
__device__ __forceinline__ uint32_t smem_u32(const void* p) {
    uint32_t a;
    asm("{ .reg .u64 t; cvta.to.shared.u64 t, %1; cvt.u32.u64 %0, t; }" : "=r"(a) : "l"(p));
    return a;
}
__device__ __forceinline__ void cp_async16(uint32_t dst, const void* src) {
    asm volatile("cp.async.cg.shared.global [%0], [%1], 16;" :: "r"(dst), "l"(src));
}
#define CP_COMMIT() asm volatile("cp.async.commit_group;" ::: "memory")
#define CP_WAIT2()  asm volatile("cp.async.wait_group 2;" ::: "memory")
#define CP_WAIT1()  asm volatile("cp.async.wait_group 1;" ::: "memory")

__device__ __forceinline__ void ldm_x4(uint32_t* r, uint32_t addr) {
    asm volatile("ldmatrix.sync.aligned.m8n8.x4.shared.b16 {%0,%1,%2,%3}, [%4];"
                 : "=r"(r[0]), "=r"(r[1]), "=r"(r[2]), "=r"(r[3]) : "r"(addr));
}
__device__ __forceinline__ void ldm_x4t(uint32_t* r, uint32_t addr) {
    asm volatile("ldmatrix.sync.aligned.m8n8.x4.trans.shared.b16 {%0,%1,%2,%3}, [%4];"
                 : "=r"(r[0]), "=r"(r[1]), "=r"(r[2]), "=r"(r[3]) : "r"(addr));
}
__device__ __forceinline__ void ldm_x2(uint32_t& r0, uint32_t& r1, uint32_t addr) {
    asm volatile("ldmatrix.sync.aligned.m8n8.x2.shared.b16 {%0,%1}, [%2];"
                 : "=r"(r0), "=r"(r1) : "r"(addr));
}
__device__ __forceinline__ void ldm_x2t(uint32_t& r0, uint32_t& r1, uint32_t addr) {
    asm volatile("ldmatrix.sync.aligned.m8n8.x2.trans.shared.b16 {%0,%1}, [%2];"
                 : "=r"(r0), "=r"(r1) : "r"(addr));
}
__device__ __forceinline__ float gelu_exact(float x) {
    return 0.5f * x * (1.0f + erff(x * 0.70710678118654752f));
}

// ---------------- fused LN0 + weight conversion ------------------------------
// blocks [0, 4096): LayerNorm rows; blocks [4096, 16384): fp32->f16 weights.
__global__ __launch_bounds__(256) void ln0_cvt_kernel(
    const float* __restrict__ x, const float* __restrict__ gw,
    const float* __restrict__ bw, __half* __restrict__ y,
    const float4* __restrict__ wqkv, const float4* __restrict__ wo,
    const float4* __restrict__ wfc0, const float4* __restrict__ wfc1,
    uint2* __restrict__ oq, uint2* __restrict__ oo,
    uint2* __restrict__ o0, uint2* __restrict__ o1)
{
    if (blockIdx.x >= L_) {
        int i = (blockIdx.x - L_) * 256 + threadIdx.x;
        const float4* src;
        uint2* dst;
        if (i < 786432)       { src = wqkv; dst = oq; }
        else if (i < 1048576) { src = wo;   dst = oo; i -= 786432; }
        else if (i < 2097152) { src = wfc0; dst = o0; i -= 1048576; }
        else                  { src = wfc1; dst = o1; i -= 2097152; }
        const float4 v = src[i];
        uint2 o;
        o.x = packf16(v.x, v.y);
        o.y = packf16(v.z, v.w);
        dst[i] = o;
        return;
    }

    __shared__ float sh[8];
    const int row  = blockIdx.x;
    const int tid  = threadIdx.x;
    const int lane = tid & 31, wp = tid >> 5;

    float4 v = *(const float4*)(x + (size_t)row * D_ + tid * 4);
    float s = v.x + v.y + v.z + v.w;
#pragma unroll
    for (int o = 16; o; o >>= 1) s += __shfl_xor_sync(0xffffffffu, s, o);
    if (lane == 0) sh[wp] = s;
    __syncthreads();
    float mean = 0.f;
#pragma unroll
    for (int i = 0; i < 8; i++) mean += sh[i];
    mean *= (1.0f / D_);
    __syncthreads();

    v.x -= mean; v.y -= mean; v.z -= mean; v.w -= mean;
    float q = v.x * v.x + v.y * v.y + v.z * v.z + v.w * v.w;
#pragma unroll
    for (int o = 16; o; o >>= 1) q += __shfl_xor_sync(0xffffffffu, q, o);
    if (lane == 0) sh[wp] = q;
    __syncthreads();
    float var = 0.f;
#pragma unroll
    for (int i = 0; i < 8; i++) var += sh[i];
    var *= (1.0f / D_);
    const float inv = rsqrtf(var + 1e-5f);

    const float4 g4 = *(const float4*)(gw + tid * 4);
    const float4 b4 = *(const float4*)(bw + tid * 4);
    uint2 o2;
    o2.x = packf16(v.x * inv * g4.x + b4.x, v.y * inv * g4.y + b4.y);
    o2.y = packf16(v.z * inv * g4.z + b4.z, v.w * inv * g4.w + b4.w);
    *(uint2*)(y + (size_t)row * D_ + tid * 4) = o2;
}

// ---------------- LayerNorm (fp32 in, f16 out) ------------------------------
__global__ __launch_bounds__(256) void ln_kernel(const float* __restrict__ x,
                                                 const float* __restrict__ gw,
                                                 const float* __restrict__ bw,
                                                 __half* __restrict__ y)
{
    __shared__ float sh[8];
    const int row  = blockIdx.x;
    const int tid  = threadIdx.x;
    const int lane = tid & 31, wp = tid >> 5;

    float4 v = *(const float4*)(x + (size_t)row * D_ + tid * 4);
    float s = v.x + v.y + v.z + v.w;
#pragma unroll
    for (int o = 16; o; o >>= 1) s += __shfl_xor_sync(0xffffffffu, s, o);
    if (lane == 0) sh[wp] = s;
    __syncthreads();
    float mean = 0.f;
#pragma unroll
    for (int i = 0; i < 8; i++) mean += sh[i];
    mean *= (1.0f / D_);
    __syncthreads();

    v.x -= mean; v.y -= mean; v.z -= mean; v.w -= mean;
    float q = v.x * v.x + v.y * v.y + v.z * v.z + v.w * v.w;
#pragma unroll
    for (int o = 16; o; o >>= 1) q += __shfl_xor_sync(0xffffffffu, q, o);
    if (lane == 0) sh[wp] = q;
    __syncthreads();
    float var = 0.f;
#pragma unroll
    for (int i = 0; i < 8; i++) var += sh[i];
    var *= (1.0f / D_);
    const float inv = rsqrtf(var + 1e-5f);

    const float4 g4 = *(const float4*)(gw + tid * 4);
    const float4 b4 = *(const float4*)(bw + tid * 4);
    uint2 o2;
    o2.x = packf16(v.x * inv * g4.x + b4.x, v.y * inv * g4.y + b4.y);
    o2.y = packf16(v.z * inv * g4.z + b4.z, v.w * inv * g4.w + b4.w);
    *(uint2*)(y + (size_t)row * D_ + tid * 4) = o2;
}

// ---------------- f16 GEMM 128x128, 4 warps of 64x64, 2 CTAs/SM -------------
// k32 chunks, 4-stage cp.async pipeline (3 in flight) — best measured config.
#define GA_BYTES (128 * 80)
#define GB_BYTES (32 * 272)
#define GEMM_SMEM (4 * (GA_BYTES + GB_BYTES))   // 75776

// q,k pre-scale: sqrt(0.125 * log2(e)) so softmax runs in exp2 domain.
#define QK_SCALE 0.42466088958239446f

template <bool BIAS, bool GELU, bool RES, bool HOUT, bool ROPE>
__global__ __launch_bounds__(128, 2) void gemm_h(
    const __half* __restrict__ A, const __half* __restrict__ B,
    const float* __restrict__ bias, const float* __restrict__ res,
    const float* __restrict__ rf, void* __restrict__ Cv, int N, int K)
{
    extern __shared__ __align__(16) char gsm[];
    const uint32_t aBase = smem_u32(gsm);
    const uint32_t bBase = aBase + 4 * GA_BYTES;

    const int tid = threadIdx.x;
    const int lane = tid & 31, wid = tid >> 5;
    const int mwarp = wid >> 1, nwarp = wid & 1;
    const int g = lane >> 2, t = lane & 3;
    const int rowBase = blockIdx.y * 128;
    const int colBase = blockIdx.x * 128;

    float acc[4][8][4];
#pragma unroll
    for (int i = 0; i < 4; i++)
#pragma unroll
        for (int j = 0; j < 8; j++)
#pragma unroll
            for (int r = 0; r < 4; r++) acc[i][j][r] = 0.f;

    const int NC = K >> 5;

    auto issue = [&](int s, int c) {
        const int k0 = c << 5;
        const uint32_t as = aBase + s * GA_BYTES;
        const uint32_t bs = bBase + s * GB_BYTES;
#pragma unroll
        for (int i = 0; i < 4; i++) {
            const int idx = i * 128 + tid;
            const int row = idx >> 2, q = idx & 3;
            cp_async16(as + row * 80 + q * 16,
                       A + (size_t)(rowBase + row) * K + k0 + q * 8);
        }
#pragma unroll
        for (int i = 0; i < 4; i++) {
            const int idx = i * 128 + tid;
            const int row = idx >> 4, q = idx & 15;
            cp_async16(bs + row * 272 + q * 16,
                       B + (size_t)(k0 + row) * N + colBase + q * 8);
        }
    };

    issue(0, 0); CP_COMMIT();
    issue(1, 1); CP_COMMIT();
    issue(2, 2); CP_COMMIT();

    uint32_t af[2][4][4], bf[2][8][2];

    auto ldfrag = [&](int fb, uint32_t aSt, uint32_t bSt, int kk) {
        const uint32_t aAddr = aSt + (mwarp * 64 + (lane & 15)) * 80
                                   + (kk + 8 * (lane >> 4)) * 2;
#pragma unroll
        for (int mt = 0; mt < 4; mt++)
            ldm_x4(af[fb][mt], aAddr + mt * 16 * 80);
        const uint32_t bAddr = bSt + (kk + (lane & 15)) * 272
                             + (nwarp * 64) * 2 + (lane >> 4) * 16;
#pragma unroll
        for (int nt2 = 0; nt2 < 4; nt2++) {
            uint32_t r[4];
            ldm_x4t(r, bAddr + nt2 * 32);
            bf[fb][2 * nt2][0] = r[0]; bf[fb][2 * nt2][1] = r[1];
            bf[fb][2 * nt2 + 1][0] = r[2]; bf[fb][2 * nt2 + 1][1] = r[3];
        }
    };

    for (int c = 0; c < NC; c++) {
        CP_WAIT2();
        __syncthreads();
        if (c + 3 < NC) issue((c + 3) & 3, c + 3);
        CP_COMMIT();

        const uint32_t aSt = aBase + (c & 3) * GA_BYTES;
        const uint32_t bSt = bBase + (c & 3) * GB_BYTES;

        ldfrag(0, aSt, bSt, 0);
#pragma unroll
        for (int kk = 0; kk < 32; kk += 16) {
            const int fb = (kk >> 4) & 1;
            if (kk + 16 < 32) ldfrag(fb ^ 1, aSt, bSt, kk + 16);
#pragma unroll
            for (int mt = 0; mt < 4; mt++)
#pragma unroll
                for (int nt = 0; nt < 8; nt++)
                    mma_f16(acc[mt][nt], af[fb][mt], bf[fb][nt][0], bf[fb][nt][1]);
        }
    }

    // epilogue
#pragma unroll
    for (int mt = 0; mt < 4; mt++) {
        const int row0 = rowBase + mwarp * 64 + mt * 16 + g;
#pragma unroll
        for (int nt = 0; nt < 8; nt++) {
            const int col = colBase + nwarp * 64 + nt * 8 + 2 * t;
#pragma unroll
            for (int half = 0; half < 2; half++) {
                const int row = row0 + half * 8;
                float vx = acc[mt][nt][half * 2 + 0];
                float vy = acc[mt][nt][half * 2 + 1];
                if (BIAS) { vx += bias[col]; vy += bias[col + 1]; }
                if (GELU) { vx = gelu_exact(vx); vy = gelu_exact(vy); }
                if (ROPE) {
                    if (col < 2048) {
                        const float2 cs = *(const float2*)(rf + (size_t)row * 64 + (col & 63));
                        const float a = vx * QK_SCALE;
                        const float b = vy * QK_SCALE;
                        vx = a * cs.x - b * cs.y;
                        vy = a * cs.y + b * cs.x;
                    }
                }
                if (RES) {
                    const float2 rr = *(const float2*)(res + (size_t)row * N + col);
                    vx += rr.x; vy += rr.y;
                }
                if (HOUT) {
                    *(__half2*)((__half*)Cv + (size_t)row * N + col) =
                        __floats2half2_rn(vx, vy);
                } else {
                    float2 o2; o2.x = vx; o2.y = vy;
                    *(float2*)((float*)Cv + (size_t)row * N + col) = o2;
                }
            }
        }
    }
}

// ---------------- f16 flash attention, 4 warps x 32 q-rows ------------------
// Grid 256 CTAs (single wave); each CTA processes 2 q-tiles sequentially.
// Softmax in exp2 domain (scale pre-folded into q,k).
#define AKV_BYTES (64 * 144)
#define ATTN_SMEM (128 * 144 + 3 * 2 * AKV_BYTES)   // 73728

__global__ __launch_bounds__(128, 2) void attn_tc_kernel(const __half* __restrict__ qkv,
                                                         __half* __restrict__ out)
{
    extern __shared__ __align__(16) char asm_[];
    const uint32_t qBase = smem_u32(asm_);
    const uint32_t kvBase = qBase + 128 * 144;

    const int tid = threadIdx.x, lane = tid & 31, wid = tid >> 5;
    const int g = lane >> 2, t = lane & 3;
    const int h = blockIdx.y, sg = blockIdx.z;
    const int m0 = wid * 32;

    for (int qi = 0; qi < 2; qi++) {
        const int q0 = sg * 1024 + (blockIdx.x + qi * 4) * 128;

        __syncthreads();   // protect SMEM reuse across q-tile iterations

#pragma unroll
        for (int i = 0; i < 8; i++) {
            const int idx = i * 128 + tid;
            const int row = idx >> 3, q = idx & 7;
            cp_async16(qBase + row * 144 + q * 16,
                       qkv + (size_t)(q0 + row) * 3072 + h * 64 + q * 8);
        }
        auto issueKV = [&](int s, int kt) {
            const int kb = sg * 1024 + kt * 64;
            const uint32_t kSt = kvBase + s * 2 * AKV_BYTES;
            const uint32_t vSt = kSt + AKV_BYTES;
#pragma unroll
            for (int i = 0; i < 4; i++) {
                const int idx = i * 128 + tid;
                const int row = idx >> 3, q = idx & 7;
                cp_async16(kSt + row * 144 + q * 16,
                           qkv + (size_t)(kb + row) * 3072 + 1024 + h * 64 + q * 8);
                cp_async16(vSt + row * 144 + q * 16,
                           qkv + (size_t)(kb + row) * 3072 + 2048 + h * 64 + q * 8);
            }
        };
        issueKV(0, 0); CP_COMMIT();
        issueKV(1, 1); CP_COMMIT();

        uint32_t qf[2][4][4];
        float mi[2][2], li[2][2];
        float ao[2][8][4];
#pragma unroll
        for (int mt = 0; mt < 2; mt++) {
            mi[mt][0] = mi[mt][1] = -3.0e38f;
            li[mt][0] = li[mt][1] = 0.f;
#pragma unroll
            for (int dt = 0; dt < 8; dt++)
#pragma unroll
                for (int r = 0; r < 4; r++) ao[mt][dt][r] = 0.f;
        }

        for (int kt = 0; kt < 16; kt++) {
            CP_WAIT1();
            __syncthreads();
            if (kt == 0) {
#pragma unroll
                for (int mt = 0; mt < 2; mt++) {
                    const uint32_t qAddr = qBase + (m0 + mt * 16 + (lane & 15)) * 144
                                         + (8 * (lane >> 4)) * 2;
#pragma unroll
                    for (int kc = 0; kc < 4; kc++)
                        ldm_x4(qf[mt][kc], qAddr + kc * 32);
                }
            }
            if (kt + 2 < 16) issueKV((kt + 2) % 3, kt + 2);
            CP_COMMIT();

            const uint32_t kSt = kvBase + (kt % 3) * 2 * AKV_BYTES;
            const uint32_t vSt = kSt + AKV_BYTES;

            float as[2][8][4];
#pragma unroll
            for (int mt = 0; mt < 2; mt++)
#pragma unroll
                for (int nt = 0; nt < 8; nt++)
#pragma unroll
                    for (int r = 0; r < 4; r++) as[mt][nt][r] = 0.f;
#pragma unroll
            for (int kc = 0; kc < 4; kc++) {
                const uint32_t kAddr = kSt + (lane & 7) * 144
                                     + (kc * 16 + 8 * ((lane >> 3) & 1)) * 2;
#pragma unroll
                for (int nt = 0; nt < 8; nt++) {
                    uint32_t b0, b1;
                    ldm_x2(b0, b1, kAddr + nt * 8 * 144);
                    mma_f16(as[0][nt], qf[0][kc], b0, b1);
                    mma_f16(as[1][nt], qf[1][kc], b0, b1);
                }
            }

#pragma unroll
            for (int mt = 0; mt < 2; mt++) {
#pragma unroll
                for (int hh = 0; hh < 2; hh++) {
                    float rm = -3.0e38f;
#pragma unroll
                    for (int nt = 0; nt < 8; nt++)
                        rm = fmaxf(rm, fmaxf(as[mt][nt][hh * 2], as[mt][nt][hh * 2 + 1]));
                    rm = fmaxf(rm, __shfl_xor_sync(0xffffffffu, rm, 1));
                    rm = fmaxf(rm, __shfl_xor_sync(0xffffffffu, rm, 2));
                    const float mn = fmaxf(mi[mt][hh], rm);
                    const float corr = exp2f(mi[mt][hh] - mn);
                    mi[mt][hh] = mn;
                    float rs = 0.f;
#pragma unroll
                    for (int nt = 0; nt < 8; nt++) {
                        const float p0 = exp2f(as[mt][nt][hh * 2] - mn);
                        const float p1 = exp2f(as[mt][nt][hh * 2 + 1] - mn);
                        as[mt][nt][hh * 2] = p0; as[mt][nt][hh * 2 + 1] = p1;
                        rs += p0 + p1;
                    }
                    rs += __shfl_xor_sync(0xffffffffu, rs, 1);
                    rs += __shfl_xor_sync(0xffffffffu, rs, 2);
                    li[mt][hh] = li[mt][hh] * corr + rs;
#pragma unroll
                    for (int dt = 0; dt < 8; dt++) {
                        ao[mt][dt][hh * 2] *= corr;
                        ao[mt][dt][hh * 2 + 1] *= corr;
                    }
                }
            }

#pragma unroll
            for (int kc = 0; kc < 4; kc++) {
                uint32_t pa[2][4];
#pragma unroll
                for (int mt = 0; mt < 2; mt++) {
                    pa[mt][0] = packf16(as[mt][2 * kc][0],     as[mt][2 * kc][1]);
                    pa[mt][1] = packf16(as[mt][2 * kc][2],     as[mt][2 * kc][3]);
                    pa[mt][2] = packf16(as[mt][2 * kc + 1][0], as[mt][2 * kc + 1][1]);
                    pa[mt][3] = packf16(as[mt][2 * kc + 1][2], as[mt][2 * kc + 1][3]);
                }
                const uint32_t vAddr = vSt + (kc * 16 + (lane & 15)) * 144;
#pragma unroll
                for (int dt = 0; dt < 8; dt++) {
                    uint32_t b0, b1;
                    ldm_x2t(b0, b1, vAddr + dt * 16);
                    mma_f16(ao[0][dt], pa[0], b0, b1);
                    mma_f16(ao[1][dt], pa[1], b0, b1);
                }
            }
        }

        // epilogue
#pragma unroll
        for (int mt = 0; mt < 2; mt++) {
            const float inv0 = 1.0f / li[mt][0];
            const float inv1 = 1.0f / li[mt][1];
            const int row0 = q0 + m0 + mt * 16 + g;
#pragma unroll
            for (int dt = 0; dt < 8; dt++) {
                const int col = h * 64 + dt * 8 + 2 * t;
                *(__half2*)(out + (size_t)row0 * 1024 + col) =
                    __floats2half2_rn(ao[mt][dt][0] * inv0, ao[mt][dt][1] * inv0);
                *(__half2*)(out + (size_t)(row0 + 8) * 1024 + col) =
                    __floats2half2_rn(ao[mt][dt][2] * inv1, ao[mt][dt][3] * inv1);
            }
        }
    }
}

// ---------------- launch ----------------------------------------------------
extern "C" void kernel_launch(void* const* d_in, const int* in_sizes, int n_in,
                              void* d_out, int out_size)
{
    const float* hs   = (const float*)d_in[0];
    const float* rope = (const float*)d_in[2];
    const float* ln0g = (const float*)d_in[3];
    const float* ln0b = (const float*)d_in[4];
    const float* ln1g = (const float*)d_in[5];
    const float* ln1b = (const float*)d_in[6];
    const float* wqkv = (const float*)d_in[7];
    const float* wo   = (const float*)d_in[8];
    const float* wfc0 = (const float*)d_in[9];
    const float* bfc0 = (const float*)d_in[10];
    const float* wfc1 = (const float*)d_in[11];
    const float* bfc1 = (const float*)d_in[12];
    float* out = (float*)d_out;

    float* h;
    __half *xln, *qkv, *attn, *y, *act, *wq, *wo_h, *w0, *w1;
    cudaGetSymbolAddress((void**)&h,    g_h);
    cudaGetSymbolAddress((void**)&xln,  g_xln);
    cudaGetSymbolAddress((void**)&qkv,  g_qkv);
    cudaGetSymbolAddress((void**)&attn, g_attn);
    cudaGetSymbolAddress((void**)&y,    g_y);
    cudaGetSymbolAddress((void**)&act,  g_act);
    cudaGetSymbolAddress((void**)&wq,   g_wq);
    cudaGetSymbolAddress((void**)&wo_h, g_wo);
    cudaGetSymbolAddress((void**)&w0,   g_w0);
    cudaGetSymbolAddress((void**)&w1,   g_w1);

    cudaFuncSetAttribute((const void*)gemm_h<false, false, false, true, true>,
                         cudaFuncAttributeMaxDynamicSharedMemorySize, GEMM_SMEM);
    cudaFuncSetAttribute((const void*)gemm_h<false, false, true, false, false>,
                         cudaFuncAttributeMaxDynamicSharedMemorySize, GEMM_SMEM);
    cudaFuncSetAttribute((const void*)gemm_h<true, true, false, true, false>,
                         cudaFuncAttributeMaxDynamicSharedMemorySize, GEMM_SMEM);
    cudaFuncSetAttribute((const void*)gemm_h<true, false, true, false, false>,
                         cudaFuncAttributeMaxDynamicSharedMemorySize, GEMM_SMEM);
    cudaFuncSetAttribute((const void*)attn_tc_kernel,
                         cudaFuncAttributeMaxDynamicSharedMemorySize, ATTN_SMEM);

    // 0. LN0 + all weights -> f16, one launch (grid-partitioned)
    ln0_cvt_kernel<<<L_ + 3145728 / 256, 256>>>(
        hs, ln0g, ln0b, xln,
        (const float4*)wqkv, (const float4*)wo, (const float4*)wfc0, (const float4*)wfc1,
        (uint2*)wq, (uint2*)wo_h, (uint2*)w0, (uint2*)w1);

    // 1. QKV (f16 out, RoPE + exp2-domain scale fused)
    gemm_h<false, false, false, true, true><<<dim3(24, 32), 128, GEMM_SMEM>>>(
        xln, wq, nullptr, nullptr, rope, qkv, 3 * D_, D_);
    // 2. attention -> f16 (256 CTAs, 2 q-tiles each: single wave)
    attn_tc_kernel<<<dim3(4, 16, 4), 128, ATTN_SMEM>>>(qkv, attn);
    // 3. h = hs + attn @ w_o   (fp32 out)
    gemm_h<false, false, true, false, false><<<dim3(8, 32), 128, GEMM_SMEM>>>(
        attn, wo_h, nullptr, hs, nullptr, h, D_, D_);
    // 4. LN1 -> f16
    ln_kernel<<<L_, 256>>>(h, ln1g, ln1b, y);
    // 5. act = gelu(y @ w_fc0 + b0)  (f16 out)
    gemm_h<true, true, false, true, false><<<dim3(32, 32), 128, GEMM_SMEM>>>(
        y, w0, bfc0, nullptr, nullptr, act, M_, D_);
    // 6. out = h + act @ w_fc1 + b1  (fp32 out)
    gemm_h<true, false, true, false, false><<<dim3(8, 32), 128, GEMM_SMEM>>>(
        act, w1, bfc1, h, nullptr, out, D_, M_);
}